// round 1
// baseline (speedup 1.0000x reference)
#include <cuda_runtime.h>
#include <math.h>
#include <stdint.h>

// ---------------- problem constants ----------------
#define HID   1024
#define QRY   1024
#define TOT   64
#define TSEQ  256
#define NTOK  (TOT*TSEQ)      // 16384 tokens
#define EXPN  8
#define TOPK  2
#define SH    4096            // shared expert intermediate
#define RI    1024            // routed expert intermediate
#define NSLOT (NTOK*TOPK)     // 32768 expert assignments
#define EPSV  1e-5f

// ---------------- device scratch (no runtime allocation allowed) ----------------
__device__ float g_h[4*2*HID];                      // FiLM hidden [4,2048]
__device__ float g_gamma[4*HID];
__device__ float g_beta[4*HID];
__device__ float g_qdot[4*EXPN];                    // query part of router logits
__device__ float g_vis_cond[(size_t)NTOK*HID];      // 64 MB
__device__ float g_h1[(size_t)NTOK*SH];             // 256 MB shared-expert intermediate
__device__ float g_outS[(size_t)NTOK*HID];          // 64 MB shared-expert output
__device__ float g_h2[(size_t)NSLOT*RI];            // 128 MB routed intermediate (slot-major)
__device__ float g_o2[(size_t)NSLOT*HID];           // 128 MB routed output (slot-major)
__device__ int   g_top_idx[NTOK*TOPK];
__device__ float g_top_w[NTOK*TOPK];
__device__ int   g_slot_tok[NSLOT];                 // slot -> token
__device__ int   g_tok_slot[NTOK*TOPK];             // token,k -> slot
__device__ int   g_count[EXPN];
__device__ int   g_off[EXPN];
__device__ int   g_fill[EXPN];
__device__ float g_prob[EXPN];
__device__ float g_zsum;

// ---------------- helpers ----------------
__device__ __forceinline__ float gelu_exact(float x) {
    return 0.5f * x * (1.0f + erff(x * 0.70710678118654752f));
}
__device__ __forceinline__ float silu_f(float x) {
    return x * (1.0f / (1.0f + expf(-x)));
}
__device__ __forceinline__ float warp_sum(float v) {
    #pragma unroll
    for (int o = 16; o; o >>= 1) v += __shfl_xor_sync(0xffffffffu, v, o);
    return v;
}

// ---------------- init ----------------
__global__ void init_kernel() {
    int t = threadIdx.x;
    if (t < EXPN) { g_count[t] = 0; g_prob[t] = 0.f; g_fill[t] = 0; }
    if (t == 0)   g_zsum = 0.f;
}

// ---------------- FiLM: h = silu(q @ w1^T + b1) ----------------
// one warp per output element; 4*2048 = 8192 warps
__global__ void film1_kernel(const float* __restrict__ q,
                             const float* __restrict__ w1,
                             const float* __restrict__ b1) {
    int w = blockIdx.x * (blockDim.x >> 5) + (threadIdx.x >> 5);
    int lane = threadIdx.x & 31;
    int b = w >> 11;            // / 2048
    int j = w & 2047;
    const float* qa = q  + (size_t)b * QRY;
    const float* wa = w1 + (size_t)j * QRY;
    float acc = 0.f;
    for (int d = lane; d < QRY; d += 32) acc += qa[d] * wa[d];
    acc = warp_sum(acc);
    if (lane == 0) g_h[b * (2*HID) + j] = silu_f(acc + b1[j]);
}

// ---------------- FiLM: gb = h @ w2^T + b2 -> gamma, beta ----------------
__global__ void film2_kernel(const float* __restrict__ w2,
                             const float* __restrict__ b2) {
    int w = blockIdx.x * (blockDim.x >> 5) + (threadIdx.x >> 5);
    int lane = threadIdx.x & 31;
    int b = w >> 11;
    int j = w & 2047;
    const float* ha = g_h + (size_t)b * (2*HID);
    const float* wa = w2  + (size_t)j * (2*HID);
    float acc = 0.f;
    for (int d = lane; d < 2*HID; d += 32) acc += ha[d] * wa[d];
    acc = warp_sum(acc);
    if (lane == 0) {
        float v = acc + b2[j];
        if (j < HID) g_gamma[b * HID + j] = v;
        else         g_beta[b * HID + (j - HID)] = v;
    }
}

// ---------------- query part of router logits: qdot[b][e] ----------------
__global__ void qdot_kernel(const float* __restrict__ q,
                            const float* __restrict__ gw) {
    int w = threadIdx.x >> 5;           // 32 warps
    int lane = threadIdx.x & 31;
    int b = w >> 3, e = w & 7;
    const float* qa = q  + (size_t)b * QRY;
    const float* wa = gw + (size_t)e * (HID + QRY) + HID;
    float acc = 0.f;
    for (int d = lane; d < QRY; d += 32) acc += qa[d] * wa[d];
    acc = warp_sum(acc);
    if (lane == 0) g_qdot[b * EXPN + e] = acc;
}

// ---------------- vis_cond = gamma * vis + beta ----------------
__global__ void viscond_kernel(const float* __restrict__ vis) {
    int n = blockIdx.x;
    int b = n >> 12;                    // token 4096-group -> original batch
    int t = threadIdx.x;                // 256 threads * float4 = 1024 floats
    float4 v  = ((const float4*)(vis       + (size_t)n * HID))[t];
    float4 g  = ((const float4*)(g_gamma   + (size_t)b * HID))[t];
    float4 be = ((const float4*)(g_beta    + (size_t)b * HID))[t];
    float4 o;
    o.x = g.x * v.x + be.x;
    o.y = g.y * v.y + be.y;
    o.z = g.z * v.z + be.z;
    o.w = g.w * v.w + be.w;
    ((float4*)(g_vis_cond + (size_t)n * HID))[t] = o;
}

// ---------------- routing: logits, softmax, top-2, loss accumulators ----------------
// one warp per token, 8 warps per block
__global__ void routing_kernel(const float* __restrict__ gw) {
    __shared__ float sgw[EXPN * HID];       // 32 KB: vis part of gate weights
    __shared__ float s_prob[EXPN];
    __shared__ int   s_cnt[EXPN];
    __shared__ float s_z;
    int tid = threadIdx.x;
    for (int i = tid; i < EXPN * HID; i += 256) {
        int e = i >> 10, d = i & 1023;
        sgw[i] = gw[(size_t)e * (HID + QRY) + d];
    }
    if (tid < EXPN) { s_prob[tid] = 0.f; s_cnt[tid] = 0; }
    if (tid == 0) s_z = 0.f;
    __syncthreads();

    int warp = tid >> 5, lane = tid & 31;
    int n = blockIdx.x * 8 + warp;
    const float4* xr = (const float4*)(g_vis_cond + (size_t)n * HID);
    float acc[EXPN];
    #pragma unroll
    for (int e = 0; e < EXPN; e++) acc[e] = 0.f;
    #pragma unroll
    for (int i = 0; i < 8; i++) {
        int p = lane + i * 32;
        float4 x = xr[p];
        #pragma unroll
        for (int e = 0; e < EXPN; e++) {
            float4 w = *(const float4*)(&sgw[e * HID + p * 4]);
            acc[e] += x.x*w.x + x.y*w.y + x.z*w.z + x.w*w.w;
        }
    }
    #pragma unroll
    for (int e = 0; e < EXPN; e++) acc[e] = warp_sum(acc[e]);

    if (lane == 0) {
        int b = n >> 12;
        float l[EXPN], s[EXPN];
        float mx = -1e30f;
        #pragma unroll
        for (int e = 0; e < EXPN; e++) {
            l[e] = acc[e] + g_qdot[b * EXPN + e];
            mx = fmaxf(mx, l[e]);
        }
        float sum = 0.f;
        #pragma unroll
        for (int e = 0; e < EXPN; e++) { s[e] = expf(l[e] - mx); sum += s[e]; }
        float inv = 1.0f / sum;
        float logz = mx + logf(sum);
        atomicAdd(&s_z, logz * logz);
        int e0 = 0;
        #pragma unroll
        for (int e = 1; e < EXPN; e++) if (s[e] > s[e0]) e0 = e;
        int e1 = (e0 == 0) ? 1 : 0;
        #pragma unroll
        for (int e = 0; e < EXPN; e++) if (e != e0 && s[e] > s[e1]) e1 = e;
        g_top_idx[2*n]   = e0;  g_top_idx[2*n+1] = e1;
        g_top_w[2*n]     = s[e0] * inv;
        g_top_w[2*n+1]   = s[e1] * inv;
        atomicAdd(&s_cnt[e0], 1);
        atomicAdd(&s_cnt[e1], 1);
        #pragma unroll
        for (int e = 0; e < EXPN; e++) atomicAdd(&s_prob[e], s[e] * inv);
    }
    __syncthreads();
    if (tid < EXPN) {
        atomicAdd(&g_prob[tid], s_prob[tid]);
        atomicAdd(&g_count[tid], s_cnt[tid]);
    }
    if (tid == 0) atomicAdd(&g_zsum, s_z);
}

// ---------------- prefix over expert counts ----------------
__global__ void prefix_kernel() {
    if (threadIdx.x == 0) {
        int o = 0;
        for (int e = 0; e < EXPN; e++) { g_off[e] = o; o += g_count[e]; g_fill[e] = 0; }
    }
}

// ---------------- fill expert slot lists ----------------
__global__ void fill_kernel() {
    int n = blockIdx.x * blockDim.x + threadIdx.x;
    #pragma unroll
    for (int k = 0; k < TOPK; k++) {
        int e = g_top_idx[2*n + k];
        int pos = atomicAdd(&g_fill[e], 1);
        int slot = g_off[e] + pos;
        g_slot_tok[slot] = n;
        g_tok_slot[2*n + k] = slot;
    }
}

// ---------------- SGEMM body: C[base+m][n] = act( A_row(m) . B[n][:] ) ----------------
// A gathered via slot_tok when non-null. B row-major [N, Kd] (K contiguous, "NT" gemm).
// 128x128 tile, BK=16, 256 threads, 8x8 per thread.
template <bool GELU>
__device__ __forceinline__ void sgemm_body(
    const float* __restrict__ A, const float* __restrict__ B, float* __restrict__ C,
    int N, int Kd, int M, int base, const int* __restrict__ slot_tok)
{
    int m0 = blockIdx.x * 128;
    if (m0 >= M) return;
    int n0 = blockIdx.y * 128;

    __shared__ float As[16][132];
    __shared__ float Bs[16][132];

    int tid = threadIdx.x;
    int tx = tid & 15, ty = tid >> 4;
    int c4 = (tid & 3) * 4;

    // per-thread tile rows (constant across K loop)
    int lr[2], arow[2];
    bool av[2];
    #pragma unroll
    for (int it = 0; it < 2; it++) {
        int s = tid + it * 256;
        lr[it] = s >> 2;
        int m = m0 + lr[it];
        av[it] = (m < M);
        int gr = base + m;
        arow[it] = av[it] ? (slot_tok ? slot_tok[gr] : gr) : 0;
    }

    float acc[8][8];
    #pragma unroll
    for (int i = 0; i < 8; i++)
        #pragma unroll
        for (int j = 0; j < 8; j++) acc[i][j] = 0.f;

    for (int k0 = 0; k0 < Kd; k0 += 16) {
        #pragma unroll
        for (int it = 0; it < 2; it++) {
            float4 v = av[it] ? *(const float4*)(A + (size_t)arow[it] * Kd + k0 + c4)
                              : make_float4(0.f, 0.f, 0.f, 0.f);
            As[c4+0][lr[it]] = v.x; As[c4+1][lr[it]] = v.y;
            As[c4+2][lr[it]] = v.z; As[c4+3][lr[it]] = v.w;
            float4 w = *(const float4*)(B + (size_t)(n0 + lr[it]) * Kd + k0 + c4);
            Bs[c4+0][lr[it]] = w.x; Bs[c4+1][lr[it]] = w.y;
            Bs[c4+2][lr[it]] = w.z; Bs[c4+3][lr[it]] = w.w;
        }
        __syncthreads();
        #pragma unroll
        for (int k = 0; k < 16; k++) {
            float ra[8], rb[8];
            *(float4*)&ra[0] = *(const float4*)&As[k][ty * 8];
            *(float4*)&ra[4] = *(const float4*)&As[k][ty * 8 + 4];
            *(float4*)&rb[0] = *(const float4*)&Bs[k][tx * 8];
            *(float4*)&rb[4] = *(const float4*)&Bs[k][tx * 8 + 4];
            #pragma unroll
            for (int i = 0; i < 8; i++)
                #pragma unroll
                for (int j = 0; j < 8; j++)
                    acc[i][j] = fmaf(ra[i], rb[j], acc[i][j]);
        }
        __syncthreads();
    }

    #pragma unroll
    for (int i = 0; i < 8; i++) {
        int m = m0 + ty * 8 + i;
        if (m < M) {
            float* cp = C + (size_t)(base + m) * N + n0 + tx * 8;
            #pragma unroll
            for (int j = 0; j < 8; j++) {
                float v = acc[i][j];
                if (GELU) v = gelu_exact(v);
                cp[j] = v;
            }
        }
    }
}

__global__ __launch_bounds__(256, 2) void k_shared_up(const float* __restrict__ swu) {
    sgemm_body<true>(g_vis_cond, swu, g_h1, SH, HID, NTOK, 0, nullptr);
}
__global__ __launch_bounds__(256, 2) void k_shared_down(const float* __restrict__ swd) {
    sgemm_body<false>(g_h1, swd, g_outS, HID, SH, NTOK, 0, nullptr);
}
__global__ __launch_bounds__(256, 2) void k_exp_up(const float* __restrict__ ewu) {
    int e = blockIdx.z;
    sgemm_body<true>(g_vis_cond, ewu + (size_t)e * RI * HID, g_h2,
                     RI, HID, g_count[e], g_off[e], g_slot_tok);
}
__global__ __launch_bounds__(256, 2) void k_exp_down(const float* __restrict__ ewd) {
    int e = blockIdx.z;
    sgemm_body<false>(g_h2, ewd + (size_t)e * HID * RI, g_o2,
                      HID, RI, g_count[e], g_off[e], nullptr);
}

// ---------------- combine + residual + LayerNorm -> y ----------------
__global__ void final_kernel(const float* __restrict__ vis,
                             const float* __restrict__ lng,
                             const float* __restrict__ lnb,
                             float* __restrict__ out) {
    __shared__ float red[2][8];
    int n = blockIdx.x, t = threadIdx.x;
    int s0 = g_tok_slot[2*n], s1 = g_tok_slot[2*n + 1];
    float w0 = g_top_w[2*n], w1 = g_top_w[2*n + 1];
    float4 a  = ((const float4*)(g_outS + (size_t)n  * HID))[t];
    float4 p0 = ((const float4*)(g_o2   + (size_t)s0 * HID))[t];
    float4 p1 = ((const float4*)(g_o2   + (size_t)s1 * HID))[t];
    float4 v  = ((const float4*)(vis    + (size_t)n  * HID))[t];
    float4 x;
    x.x = a.x + w0 * p0.x + w1 * p1.x + v.x;
    x.y = a.y + w0 * p0.y + w1 * p1.y + v.y;
    x.z = a.z + w0 * p0.z + w1 * p1.z + v.z;
    x.w = a.w + w0 * p0.w + w1 * p1.w + v.w;
    float sm = x.x + x.y + x.z + x.w;
    float sq = x.x*x.x + x.y*x.y + x.z*x.z + x.w*x.w;
    sm = warp_sum(sm);
    sq = warp_sum(sq);
    int lane = t & 31, wp = t >> 5;
    if (lane == 0) { red[0][wp] = sm; red[1][wp] = sq; }
    __syncthreads();
    if (t == 0) {
        float S = 0.f, Q = 0.f;
        #pragma unroll
        for (int i = 0; i < 8; i++) { S += red[0][i]; Q += red[1][i]; }
        red[0][0] = S; red[1][0] = Q;
    }
    __syncthreads();
    float mean = red[0][0] * (1.0f / HID);
    float var  = red[1][0] * (1.0f / HID) - mean * mean;
    float inv  = rsqrtf(var + EPSV);
    float4 g  = ((const float4*)lng)[t];
    float4 bb = ((const float4*)lnb)[t];
    float4 y;
    y.x = (x.x - mean) * inv * g.x + bb.x;
    y.y = (x.y - mean) * inv * g.y + bb.y;
    y.z = (x.z - mean) * inv * g.z + bb.z;
    y.w = (x.w - mean) * inv * g.w + bb.w;
    ((float4*)(out + (size_t)n * HID))[t] = y;
}

// ---------------- losses ----------------
__global__ void loss_kernel(float* __restrict__ out, int out_size) {
    if (threadIdx.x == 0 && out_size >= NTOK * HID + 2) {
        float lb = 0.f;
        for (int e = 0; e < EXPN; e++)
            lb += ((float)g_count[e] / (float)NSLOT) * (g_prob[e] / (float)NTOK);
        out[out_size - 2] = (float)EXPN * lb;
        out[out_size - 1] = g_zsum / (float)NTOK;
    }
}

// ---------------- launch ----------------
extern "C" void kernel_launch(void* const* d_in, const int* in_sizes, int n_in,
                              void* d_out, int out_size) {
    const float* vis  = (const float*)d_in[0];
    const float* q    = (const float*)d_in[1];
    const float* fw1  = (const float*)d_in[2];
    const float* fb1  = (const float*)d_in[3];
    const float* fw2  = (const float*)d_in[4];
    const float* fb2  = (const float*)d_in[5];
    const float* gw   = (const float*)d_in[6];
    const float* swu  = (const float*)d_in[7];
    const float* swd  = (const float*)d_in[8];
    const float* ewu  = (const float*)d_in[9];
    const float* ewd  = (const float*)d_in[10];
    const float* lng  = (const float*)d_in[11];
    const float* lnb  = (const float*)d_in[12];
    float* out = (float*)d_out;

    init_kernel<<<1, 32>>>();
    film1_kernel<<<1024, 256>>>(q, fw1, fb1);
    film2_kernel<<<1024, 256>>>(fw2, fb2);
    qdot_kernel<<<1, 1024>>>(q, gw);
    viscond_kernel<<<NTOK, 256>>>(vis);
    routing_kernel<<<NTOK / 8, 256>>>(gw);
    prefix_kernel<<<1, 1>>>();
    fill_kernel<<<NTOK / 256, 256>>>();

    k_shared_up  <<<dim3(NTOK / 128, SH  / 128, 1), 256>>>(swu);
    k_shared_down<<<dim3(NTOK / 128, HID / 128, 1), 256>>>(swd);
    k_exp_up     <<<dim3(NTOK / 128, RI  / 128, EXPN), 256>>>(ewu);
    k_exp_down   <<<dim3(NTOK / 128, HID / 128, EXPN), 256>>>(ewd);

    final_kernel<<<NTOK, 256>>>(vis, lng, lnb, out);
    loss_kernel<<<1, 32>>>(out, out_size);
}

// round 3
// speedup vs baseline: 1.8374x; 1.8374x over previous
#include <cuda_runtime.h>
#include <cuda_bf16.h>
#include <math.h>
#include <stdint.h>

// ---------------- problem constants ----------------
#define HID   1024
#define QRY   1024
#define NTOK  16384           // 64*256 tokens
#define EXPN  8
#define TOPK  2
#define SH    4096            // shared expert intermediate
#define RI    1024            // routed expert intermediate
#define NSLOT (NTOK*TOPK)     // 32768 expert assignments
#define EPSV  1e-5f

// GEMM tiling: 128x128x16, static 48KB smem (no cudaFuncSetAttribute needed)
#define BM 128
#define BN 128
#define BK 16
#define ASTR 24               // smem row stride in bf16 elems (pad 16->24, 48B: conflict-free)
#define TILE_EL (BM*ASTR)     // 3072 elems = 6144 bytes per array
// 2 buffers * 4 arrays * 6144 = 49152 bytes = 48KB static shared

// ---------------- device scratch ----------------
__device__ float g_h[4*2*HID];
__device__ float g_gamma[4*HID];
__device__ float g_beta[4*HID];
__device__ float g_qdot[4*EXPN];
__device__ float g_vis_cond[(size_t)NTOK*HID];          // exact fp32 (routing)
__device__ __nv_bfloat16 g_visH[(size_t)NTOK*HID];      // bf16 hi/lo splits
__device__ __nv_bfloat16 g_visL[(size_t)NTOK*HID];
__device__ __nv_bfloat16 g_h1H[(size_t)NTOK*SH];
__device__ __nv_bfloat16 g_h1L[(size_t)NTOK*SH];
__device__ float g_outS[(size_t)NTOK*HID];
__device__ __nv_bfloat16 g_h2H[(size_t)NSLOT*RI];
__device__ __nv_bfloat16 g_h2L[(size_t)NSLOT*RI];
__device__ float g_o2[(size_t)NSLOT*HID];
// split weights
__device__ __nv_bfloat16 g_swuH[(size_t)SH*HID],  g_swuL[(size_t)SH*HID];
__device__ __nv_bfloat16 g_swdH[(size_t)HID*SH],  g_swdL[(size_t)HID*SH];
__device__ __nv_bfloat16 g_ewuH[(size_t)EXPN*RI*HID], g_ewuL[(size_t)EXPN*RI*HID];
__device__ __nv_bfloat16 g_ewdH[(size_t)EXPN*HID*RI], g_ewdL[(size_t)EXPN*HID*RI];
// routing metadata
__device__ int   g_top_idx[NTOK*TOPK];
__device__ float g_top_w[NTOK*TOPK];
__device__ int   g_slot_tok[NSLOT];
__device__ int   g_tok_slot[NTOK*TOPK];
__device__ int   g_count[EXPN];
__device__ int   g_off[EXPN];
__device__ int   g_fill[EXPN];
__device__ float g_prob[EXPN];
__device__ float g_zsum;

// ---------------- helpers ----------------
__device__ __forceinline__ float gelu_exact(float x) {
    return 0.5f * x * (1.0f + erff(x * 0.70710678118654752f));
}
__device__ __forceinline__ float silu_f(float x) {
    return x * (1.0f / (1.0f + expf(-x)));
}
__device__ __forceinline__ float warp_sum(float v) {
    #pragma unroll
    for (int o = 16; o; o >>= 1) v += __shfl_xor_sync(0xffffffffu, v, o);
    return v;
}
__device__ __forceinline__ void cpa16(uint32_t dst, const void* src) {
    asm volatile("cp.async.cg.shared.global [%0], [%1], 16;\n" :: "r"(dst), "l"(src));
}
__device__ __forceinline__ void cp_commit() {
    asm volatile("cp.async.commit_group;\n" ::);
}
template<int N>
__device__ __forceinline__ void cp_wait() {
    asm volatile("cp.async.wait_group %0;\n" :: "n"(N));
}
__device__ __forceinline__ void ldsm4(uint32_t& r0, uint32_t& r1, uint32_t& r2, uint32_t& r3, uint32_t a) {
    asm volatile("ldmatrix.sync.aligned.m8n8.x4.shared.b16 {%0,%1,%2,%3}, [%4];\n"
                 : "=r"(r0), "=r"(r1), "=r"(r2), "=r"(r3) : "r"(a));
}
__device__ __forceinline__ void mma_bf16(float* c, const uint32_t* a, uint32_t b0, uint32_t b1) {
    asm volatile(
        "mma.sync.aligned.m16n8k16.row.col.f32.bf16.bf16.f32 "
        "{%0,%1,%2,%3}, {%4,%5,%6,%7}, {%8,%9}, {%0,%1,%2,%3};\n"
        : "+f"(c[0]), "+f"(c[1]), "+f"(c[2]), "+f"(c[3])
        : "r"(a[0]), "r"(a[1]), "r"(a[2]), "r"(a[3]), "r"(b0), "r"(b1));
}

// ---------------- init ----------------
__global__ void init_kernel() {
    int t = threadIdx.x;
    if (t < EXPN) { g_count[t] = 0; g_prob[t] = 0.f; g_fill[t] = 0; }
    if (t == 0)   g_zsum = 0.f;
}

// ---------------- weight split: fp32 -> bf16 hi/lo ----------------
__global__ void split4_kernel(const float* __restrict__ s,
                              __nv_bfloat16* __restrict__ h,
                              __nv_bfloat16* __restrict__ l, int n4) {
    int i = blockIdx.x * blockDim.x + threadIdx.x;
    if (i >= n4) return;
    float4 v = ((const float4*)s)[i];
    __nv_bfloat16 h0 = __float2bfloat16_rn(v.x);
    __nv_bfloat16 h1 = __float2bfloat16_rn(v.y);
    __nv_bfloat16 h2 = __float2bfloat16_rn(v.z);
    __nv_bfloat16 h3 = __float2bfloat16_rn(v.w);
    __nv_bfloat162 hh0; hh0.x = h0; hh0.y = h1;
    __nv_bfloat162 hh1; hh1.x = h2; hh1.y = h3;
    ((__nv_bfloat162*)h)[2*i]   = hh0;
    ((__nv_bfloat162*)h)[2*i+1] = hh1;
    __nv_bfloat162 ll0, ll1;
    ll0.x = __float2bfloat16_rn(v.x - __bfloat162float(h0));
    ll0.y = __float2bfloat16_rn(v.y - __bfloat162float(h1));
    ll1.x = __float2bfloat16_rn(v.z - __bfloat162float(h2));
    ll1.y = __float2bfloat16_rn(v.w - __bfloat162float(h3));
    ((__nv_bfloat162*)l)[2*i]   = ll0;
    ((__nv_bfloat162*)l)[2*i+1] = ll1;
}

// ---------------- FiLM ----------------
__global__ void film1_kernel(const float* __restrict__ q,
                             const float* __restrict__ w1,
                             const float* __restrict__ b1) {
    int w = blockIdx.x * (blockDim.x >> 5) + (threadIdx.x >> 5);
    int lane = threadIdx.x & 31;
    int b = w >> 11, j = w & 2047;
    const float* qa = q  + (size_t)b * QRY;
    const float* wa = w1 + (size_t)j * QRY;
    float acc = 0.f;
    for (int d = lane; d < QRY; d += 32) acc += qa[d] * wa[d];
    acc = warp_sum(acc);
    if (lane == 0) g_h[b * (2*HID) + j] = silu_f(acc + b1[j]);
}
__global__ void film2_kernel(const float* __restrict__ w2,
                             const float* __restrict__ b2) {
    int w = blockIdx.x * (blockDim.x >> 5) + (threadIdx.x >> 5);
    int lane = threadIdx.x & 31;
    int b = w >> 11, j = w & 2047;
    const float* ha = g_h + (size_t)b * (2*HID);
    const float* wa = w2  + (size_t)j * (2*HID);
    float acc = 0.f;
    for (int d = lane; d < 2*HID; d += 32) acc += ha[d] * wa[d];
    acc = warp_sum(acc);
    if (lane == 0) {
        float v = acc + b2[j];
        if (j < HID) g_gamma[b * HID + j] = v;
        else         g_beta[b * HID + (j - HID)] = v;
    }
}
__global__ void qdot_kernel(const float* __restrict__ q,
                            const float* __restrict__ gw) {
    int w = threadIdx.x >> 5;
    int lane = threadIdx.x & 31;
    int b = w >> 3, e = w & 7;
    const float* qa = q  + (size_t)b * QRY;
    const float* wa = gw + (size_t)e * (HID + QRY) + HID;
    float acc = 0.f;
    for (int d = lane; d < QRY; d += 32) acc += qa[d] * wa[d];
    acc = warp_sum(acc);
    if (lane == 0) g_qdot[b * EXPN + e] = acc;
}

// ---------------- vis_cond = gamma*vis + beta (fp32 + bf16 splits) ----------------
__global__ void viscond_kernel(const float* __restrict__ vis) {
    int n = blockIdx.x;
    int b = n >> 12;
    int t = threadIdx.x;
    size_t rb = (size_t)n * HID;
    float4 v  = ((const float4*)(vis     + rb))[t];
    float4 g  = ((const float4*)(g_gamma + (size_t)b * HID))[t];
    float4 be = ((const float4*)(g_beta  + (size_t)b * HID))[t];
    float4 o;
    o.x = g.x * v.x + be.x; o.y = g.y * v.y + be.y;
    o.z = g.z * v.z + be.z; o.w = g.w * v.w + be.w;
    ((float4*)(g_vis_cond + rb))[t] = o;
    __nv_bfloat16 h0 = __float2bfloat16_rn(o.x), h1 = __float2bfloat16_rn(o.y);
    __nv_bfloat16 h2 = __float2bfloat16_rn(o.z), h3 = __float2bfloat16_rn(o.w);
    __nv_bfloat162 hh0; hh0.x = h0; hh0.y = h1;
    __nv_bfloat162 hh1; hh1.x = h2; hh1.y = h3;
    ((__nv_bfloat162*)(g_visH + rb))[2*t]   = hh0;
    ((__nv_bfloat162*)(g_visH + rb))[2*t+1] = hh1;
    __nv_bfloat162 ll0, ll1;
    ll0.x = __float2bfloat16_rn(o.x - __bfloat162float(h0));
    ll0.y = __float2bfloat16_rn(o.y - __bfloat162float(h1));
    ll1.x = __float2bfloat16_rn(o.z - __bfloat162float(h2));
    ll1.y = __float2bfloat16_rn(o.w - __bfloat162float(h3));
    ((__nv_bfloat162*)(g_visL + rb))[2*t]   = ll0;
    ((__nv_bfloat162*)(g_visL + rb))[2*t+1] = ll1;
}

// ---------------- routing (exact fp32) ----------------
__global__ void routing_kernel(const float* __restrict__ gw) {
    __shared__ float sgw[EXPN * HID];
    __shared__ float s_prob[EXPN];
    __shared__ int   s_cnt[EXPN];
    __shared__ float s_z;
    int tid = threadIdx.x;
    for (int i = tid; i < EXPN * HID; i += 256) {
        int e = i >> 10, d = i & 1023;
        sgw[i] = gw[(size_t)e * (HID + QRY) + d];
    }
    if (tid < EXPN) { s_prob[tid] = 0.f; s_cnt[tid] = 0; }
    if (tid == 0) s_z = 0.f;
    __syncthreads();

    int warp = tid >> 5, lane = tid & 31;
    int n = blockIdx.x * 8 + warp;
    const float4* xr = (const float4*)(g_vis_cond + (size_t)n * HID);
    float acc[EXPN];
    #pragma unroll
    for (int e = 0; e < EXPN; e++) acc[e] = 0.f;
    #pragma unroll
    for (int i = 0; i < 8; i++) {
        int p = lane + i * 32;
        float4 x = xr[p];
        #pragma unroll
        for (int e = 0; e < EXPN; e++) {
            float4 w = *(const float4*)(&sgw[e * HID + p * 4]);
            acc[e] += x.x*w.x + x.y*w.y + x.z*w.z + x.w*w.w;
        }
    }
    #pragma unroll
    for (int e = 0; e < EXPN; e++) acc[e] = warp_sum(acc[e]);

    if (lane == 0) {
        int b = n >> 12;
        float l[EXPN], s[EXPN];
        float mx = -1e30f;
        #pragma unroll
        for (int e = 0; e < EXPN; e++) {
            l[e] = acc[e] + g_qdot[b * EXPN + e];
            mx = fmaxf(mx, l[e]);
        }
        float sum = 0.f;
        #pragma unroll
        for (int e = 0; e < EXPN; e++) { s[e] = expf(l[e] - mx); sum += s[e]; }
        float inv = 1.0f / sum;
        float logz = mx + logf(sum);
        atomicAdd(&s_z, logz * logz);
        int e0 = 0;
        #pragma unroll
        for (int e = 1; e < EXPN; e++) if (s[e] > s[e0]) e0 = e;
        int e1 = (e0 == 0) ? 1 : 0;
        #pragma unroll
        for (int e = 0; e < EXPN; e++) if (e != e0 && s[e] > s[e1]) e1 = e;
        g_top_idx[2*n]   = e0;  g_top_idx[2*n+1] = e1;
        g_top_w[2*n]     = s[e0] * inv;
        g_top_w[2*n+1]   = s[e1] * inv;
        atomicAdd(&s_cnt[e0], 1);
        atomicAdd(&s_cnt[e1], 1);
        #pragma unroll
        for (int e = 0; e < EXPN; e++) atomicAdd(&s_prob[e], s[e] * inv);
    }
    __syncthreads();
    if (tid < EXPN) {
        atomicAdd(&g_prob[tid], s_prob[tid]);
        atomicAdd(&g_count[tid], s_cnt[tid]);
    }
    if (tid == 0) atomicAdd(&g_zsum, s_z);
}

__global__ void prefix_kernel() {
    if (threadIdx.x == 0) {
        int o = 0;
        for (int e = 0; e < EXPN; e++) { g_off[e] = o; o += g_count[e]; g_fill[e] = 0; }
    }
}
__global__ void fill_kernel() {
    int n = blockIdx.x * blockDim.x + threadIdx.x;
    #pragma unroll
    for (int k = 0; k < TOPK; k++) {
        int e = g_top_idx[2*n + k];
        int pos = atomicAdd(&g_fill[e], 1);
        int slot = g_off[e] + pos;
        g_slot_tok[slot] = n;
        g_tok_slot[2*n + k] = slot;
    }
}

// ---------------- bf16x3 tensor-core GEMM ----------------
// C[base+m][n] = act( A_row(m) . B_row(n) ), A,B pre-split hi/lo bf16, K-major.
// acc += Ah*Bh + Al*Bh + Ah*Bl  (drops ~2^-18 term)
// 128x128x16 tile, 256 threads (8 warps, 2x4), warp tile 64x32, mma m16n8k16.
// Static 48KB smem, double buffered.
template <bool GELU, bool SPLIT>
__device__ __forceinline__ void gemm_body(
    const __nv_bfloat16* __restrict__ Ah, const __nv_bfloat16* __restrict__ Al,
    const __nv_bfloat16* __restrict__ Bh, const __nv_bfloat16* __restrict__ Bl,
    float* __restrict__ Cf, __nv_bfloat16* __restrict__ Ch, __nv_bfloat16* __restrict__ Cl,
    int N, int K, int M, int base, const int* __restrict__ slot_tok)
{
    int m0 = blockIdx.x * BM;
    if (m0 >= M) return;
    int n0 = blockIdx.y * BN;

    __shared__ __align__(16) __nv_bfloat16 smem[2 * 4 * TILE_EL];   // 49152 bytes
    uint32_t sbase = (uint32_t)__cvta_generic_to_shared(smem);

    int tid = threadIdx.x;
    int lane = tid & 31, warp = tid >> 5;
    int wm = warp >> 2, wn = warp & 3;

    // --- per-thread global load pointers (row constant across k) ---
    // 256 threads cover 128 rows x 2 groups of 8 elems (16B) per array.
    int row = tid >> 1;
    int cg  = (tid & 1) * 8;
    int m = m0 + row;
    int gm = (m < M) ? m : (M - 1);
    int ar = slot_tok ? slot_tok[base + gm] : (base + gm);
    const __nv_bfloat16* pAh = Ah + (size_t)ar * K + cg;
    const __nv_bfloat16* pAl = Al + (size_t)ar * K + cg;
    const __nv_bfloat16* pBh = Bh + (size_t)(n0 + row) * K + cg;
    const __nv_bfloat16* pBl = Bl + (size_t)(n0 + row) * K + cg;
    uint32_t soff = (uint32_t)(row * ASTR + cg) * 2;   // bytes

    auto load_tiles = [&](int buf, int k0) {
        uint32_t sb = sbase + (uint32_t)buf * 4 * TILE_EL * 2;
        cpa16(sb + 0*TILE_EL*2 + soff, pAh + k0);
        cpa16(sb + 1*TILE_EL*2 + soff, pAl + k0);
        cpa16(sb + 2*TILE_EL*2 + soff, pBh + k0);
        cpa16(sb + 3*TILE_EL*2 + soff, pBl + k0);
    };

    // ldmatrix lane address components
    int a_row = (lane & 7) + ((lane >> 3) & 1) * 8;
    int a_col = ((lane >> 4) & 1) * 8;
    int b_row = (lane & 7) + ((lane >> 4) & 1) * 8;
    int b_col = ((lane >> 3) & 1) * 8;

    float acc[4][4][4];
    #pragma unroll
    for (int i = 0; i < 4; i++)
        #pragma unroll
        for (int j = 0; j < 4; j++)
            #pragma unroll
            for (int r = 0; r < 4; r++) acc[i][j][r] = 0.f;

    int KITERS = K / BK;
    load_tiles(0, 0);
    cp_commit();

    int buf = 0;
    for (int kit = 0; kit < KITERS; kit++) {
        if (kit + 1 < KITERS) {
            load_tiles(buf ^ 1, (kit + 1) * BK);
            cp_commit();
            cp_wait<1>();
        } else {
            cp_wait<0>();
        }
        __syncthreads();

        uint32_t sAh = sbase + (uint32_t)(buf*4 + 0) * TILE_EL * 2;
        uint32_t sAl = sbase + (uint32_t)(buf*4 + 1) * TILE_EL * 2;
        uint32_t sBh = sbase + (uint32_t)(buf*4 + 2) * TILE_EL * 2;
        uint32_t sBl = sbase + (uint32_t)(buf*4 + 3) * TILE_EL * 2;

        uint32_t aH[4][4], aL[4][4];
        #pragma unroll
        for (int mi = 0; mi < 4; mi++) {
            uint32_t off = (uint32_t)((wm*64 + mi*16 + a_row) * ASTR + a_col) * 2;
            ldsm4(aH[mi][0], aH[mi][1], aH[mi][2], aH[mi][3], sAh + off);
            ldsm4(aL[mi][0], aL[mi][1], aL[mi][2], aL[mi][3], sAl + off);
        }
        uint32_t bH[8], bL[8];
        #pragma unroll
        for (int np = 0; np < 2; np++) {
            uint32_t off = (uint32_t)((wn*32 + np*16 + b_row) * ASTR + b_col) * 2;
            ldsm4(bH[np*4+0], bH[np*4+1], bH[np*4+2], bH[np*4+3], sBh + off);
            ldsm4(bL[np*4+0], bL[np*4+1], bL[np*4+2], bL[np*4+3], sBl + off);
        }
        #pragma unroll
        for (int mi = 0; mi < 4; mi++) {
            #pragma unroll
            for (int ni = 0; ni < 4; ni++) {
                int bi = (ni >> 1) * 4 + (ni & 1) * 2;
                mma_bf16(acc[mi][ni], aH[mi], bH[bi], bH[bi+1]);
                mma_bf16(acc[mi][ni], aL[mi], bH[bi], bH[bi+1]);
                mma_bf16(acc[mi][ni], aH[mi], bL[bi], bL[bi+1]);
            }
        }
        __syncthreads();
        buf ^= 1;
    }

    // --- epilogue ---
    int lr = lane >> 2;
    int lc = (lane & 3) * 2;
    #pragma unroll
    for (int mi = 0; mi < 4; mi++) {
        #pragma unroll
        for (int hi2 = 0; hi2 < 2; hi2++) {
            int mm = m0 + wm*64 + mi*16 + lr + hi2*8;
            if (mm >= M) continue;
            size_t rowb = (size_t)(base + mm) * N;
            #pragma unroll
            for (int ni = 0; ni < 4; ni++) {
                int col = n0 + wn*32 + ni*8 + lc;
                float v0 = acc[mi][ni][hi2*2 + 0];
                float v1 = acc[mi][ni][hi2*2 + 1];
                if (GELU) { v0 = gelu_exact(v0); v1 = gelu_exact(v1); }
                if (SPLIT) {
                    __nv_bfloat16 h0 = __float2bfloat16_rn(v0);
                    __nv_bfloat16 h1 = __float2bfloat16_rn(v1);
                    __nv_bfloat162 hv; hv.x = h0; hv.y = h1;
                    *(__nv_bfloat162*)(Ch + rowb + col) = hv;
                    __nv_bfloat162 lv;
                    lv.x = __float2bfloat16_rn(v0 - __bfloat162float(h0));
                    lv.y = __float2bfloat16_rn(v1 - __bfloat162float(h1));
                    *(__nv_bfloat162*)(Cl + rowb + col) = lv;
                } else {
                    float2 fv; fv.x = v0; fv.y = v1;
                    *(float2*)(Cf + rowb + col) = fv;
                }
            }
        }
    }
}

__global__ __launch_bounds__(256, 1) void k_shared_up() {
    gemm_body<true, true>(g_visH, g_visL, g_swuH, g_swuL,
                          nullptr, g_h1H, g_h1L, SH, HID, NTOK, 0, nullptr);
}
__global__ __launch_bounds__(256, 1) void k_shared_down() {
    gemm_body<false, false>(g_h1H, g_h1L, g_swdH, g_swdL,
                            g_outS, nullptr, nullptr, HID, SH, NTOK, 0, nullptr);
}
__global__ __launch_bounds__(256, 1) void k_exp_up() {
    int e = blockIdx.z;
    gemm_body<true, true>(g_visH, g_visL,
                          g_ewuH + (size_t)e * RI * HID, g_ewuL + (size_t)e * RI * HID,
                          nullptr, g_h2H, g_h2L, RI, HID, g_count[e], g_off[e], g_slot_tok);
}
__global__ __launch_bounds__(256, 1) void k_exp_down() {
    int e = blockIdx.z;
    gemm_body<false, false>(g_h2H, g_h2L,
                            g_ewdH + (size_t)e * HID * RI, g_ewdL + (size_t)e * HID * RI,
                            g_o2, nullptr, nullptr, HID, RI, g_count[e], g_off[e], nullptr);
}

// ---------------- combine + residual + LayerNorm ----------------
__global__ void final_kernel(const float* __restrict__ vis,
                             const float* __restrict__ lng,
                             const float* __restrict__ lnb,
                             float* __restrict__ out) {
    __shared__ float red[2][8];
    int n = blockIdx.x, t = threadIdx.x;
    int s0 = g_tok_slot[2*n], s1 = g_tok_slot[2*n + 1];
    float w0 = g_top_w[2*n], w1 = g_top_w[2*n + 1];
    float4 a  = ((const float4*)(g_outS + (size_t)n  * HID))[t];
    float4 p0 = ((const float4*)(g_o2   + (size_t)s0 * HID))[t];
    float4 p1 = ((const float4*)(g_o2   + (size_t)s1 * HID))[t];
    float4 v  = ((const float4*)(vis    + (size_t)n  * HID))[t];
    float4 x;
    x.x = a.x + w0 * p0.x + w1 * p1.x + v.x;
    x.y = a.y + w0 * p0.y + w1 * p1.y + v.y;
    x.z = a.z + w0 * p0.z + w1 * p1.z + v.z;
    x.w = a.w + w0 * p0.w + w1 * p1.w + v.w;
    float sm = x.x + x.y + x.z + x.w;
    float sq = x.x*x.x + x.y*x.y + x.z*x.z + x.w*x.w;
    sm = warp_sum(sm);
    sq = warp_sum(sq);
    int lane = t & 31, wp = t >> 5;
    if (lane == 0) { red[0][wp] = sm; red[1][wp] = sq; }
    __syncthreads();
    if (t == 0) {
        float S = 0.f, Q = 0.f;
        #pragma unroll
        for (int i = 0; i < 8; i++) { S += red[0][i]; Q += red[1][i]; }
        red[0][0] = S; red[1][0] = Q;
    }
    __syncthreads();
    float mean = red[0][0] * (1.0f / HID);
    float var  = red[1][0] * (1.0f / HID) - mean * mean;
    float inv  = rsqrtf(var + EPSV);
    float4 g  = ((const float4*)lng)[t];
    float4 bb = ((const float4*)lnb)[t];
    float4 y;
    y.x = (x.x - mean) * inv * g.x + bb.x;
    y.y = (x.y - mean) * inv * g.y + bb.y;
    y.z = (x.z - mean) * inv * g.z + bb.z;
    y.w = (x.w - mean) * inv * g.w + bb.w;
    ((float4*)(out + (size_t)n * HID))[t] = y;
}

__global__ void loss_kernel(float* __restrict__ out, int out_size) {
    if (threadIdx.x == 0 && out_size >= NTOK * HID + 2) {
        float lb = 0.f;
        for (int e = 0; e < EXPN; e++)
            lb += ((float)g_count[e] / (float)NSLOT) * (g_prob[e] / (float)NTOK);
        out[out_size - 2] = (float)EXPN * lb;
        out[out_size - 1] = g_zsum / (float)NTOK;
    }
}

// ---------------- launch ----------------
extern "C" void kernel_launch(void* const* d_in, const int* in_sizes, int n_in,
                              void* d_out, int out_size) {
    const float* vis  = (const float*)d_in[0];
    const float* q    = (const float*)d_in[1];
    const float* fw1  = (const float*)d_in[2];
    const float* fb1  = (const float*)d_in[3];
    const float* fw2  = (const float*)d_in[4];
    const float* fb2  = (const float*)d_in[5];
    const float* gw   = (const float*)d_in[6];
    const float* swu  = (const float*)d_in[7];
    const float* swd  = (const float*)d_in[8];
    const float* ewu  = (const float*)d_in[9];
    const float* ewd  = (const float*)d_in[10];
    const float* lng  = (const float*)d_in[11];
    const float* lnb  = (const float*)d_in[12];
    float* out = (float*)d_out;

    init_kernel<<<1, 32>>>();

    // weight splits (independent of token path)
    __nv_bfloat16 *swuH, *swuL, *swdH, *swdL, *ewuH, *ewuL, *ewdH, *ewdL;
    cudaGetSymbolAddress((void**)&swuH, g_swuH); cudaGetSymbolAddress((void**)&swuL, g_swuL);
    cudaGetSymbolAddress((void**)&swdH, g_swdH); cudaGetSymbolAddress((void**)&swdL, g_swdL);
    cudaGetSymbolAddress((void**)&ewuH, g_ewuH); cudaGetSymbolAddress((void**)&ewuL, g_ewuL);
    cudaGetSymbolAddress((void**)&ewdH, g_ewdH); cudaGetSymbolAddress((void**)&ewdL, g_ewdL);
    split4_kernel<<<(SH*HID/4 + 255)/256, 256>>>(swu, swuH, swuL, SH*HID/4);
    split4_kernel<<<(HID*SH/4 + 255)/256, 256>>>(swd, swdH, swdL, HID*SH/4);
    split4_kernel<<<(EXPN*RI*HID/4 + 255)/256, 256>>>(ewu, ewuH, ewuL, EXPN*RI*HID/4);
    split4_kernel<<<(EXPN*HID*RI/4 + 255)/256, 256>>>(ewd, ewdH, ewdL, EXPN*HID*RI/4);

    film1_kernel<<<1024, 256>>>(q, fw1, fb1);
    film2_kernel<<<1024, 256>>>(fw2, fb2);
    qdot_kernel<<<1, 1024>>>(q, gw);
    viscond_kernel<<<NTOK, 256>>>(vis);
    routing_kernel<<<NTOK / 8, 256>>>(gw);
    prefix_kernel<<<1, 1>>>();
    fill_kernel<<<NTOK / 256, 256>>>();

    k_shared_up  <<<dim3(NTOK / BM, SH  / BN, 1), 256>>>();
    k_shared_down<<<dim3(NTOK / BM, HID / BN, 1), 256>>>();
    k_exp_up     <<<dim3(NTOK / BM, RI  / BN, EXPN), 256>>>();
    k_exp_down   <<<dim3(NTOK / BM, HID / BN, EXPN), 256>>>();

    final_kernel<<<NTOK, 256>>>(vis, lng, lnb, out);
    loss_kernel<<<1, 32>>>(out, out_size);
}